// round 7
// baseline (speedup 1.0000x reference)
#include <cuda_runtime.h>
#include <cstdint>

// Affine-collapse: weight(x) = alpha*x + beta (4-layer affine MLP, no activations).
// out[row] = alpha * S2/S1^2 + beta, S1 = sum(x), S2 = sum(x^2), row = 2048 floats.
//
// R7: the LDG path plateaued at ~2 TB/s (per-SM outstanding-line cap). Stream
// each CTA's 16KB (2 rows) with ONE cp.async.bulk into smem (mbarrier
// completion), then reduce from smem with conflict-free LDS.128. Block 0 still
// computes (alpha, beta) once and publishes via device flag.

#define HIDDEN 32
#define L 2048
#define L_VEC4 (L / 4)        // 512 float4 per row
#define ROWS_PER_CTA 2
#define THREADS 256
#define TILE_BYTES (ROWS_PER_CTA * L * 4)   // 16384

__device__ float g_ab[2];
__device__ int   g_flag;   // set once per launch; identical values -> deterministic

__device__ __forceinline__ uint32_t smem_u32(const void* p) {
    return (uint32_t)__cvta_generic_to_shared(p);
}

__global__ __launch_bounds__(THREADS) void incidence_fused_kernel(
    const float* __restrict__ x,
    const float* __restrict__ w1, const float* __restrict__ b1,
    const float* __restrict__ w2, const float* __restrict__ b2,
    const float* __restrict__ w3, const float* __restrict__ b3,
    const float* __restrict__ w4, const float* __restrict__ b4,
    float* __restrict__ out, int rows)
{
    // ================= block 0: weight collapse, once on the chip ==========
    if (blockIdx.x == 0) {
        __shared__ float rv[8][32], rc[8][32];
        __shared__ float v2s[32], c2s[32];

        const int k = threadIdx.x & 31;   // output unit
        const int g = threadIdx.x >> 5;   // input chunk (4 units each)

        float w2r[4], w3r[4], va[4], ca[4];
        #pragma unroll
        for (int j = 0; j < 4; j++) w2r[j] = w2[(4 * g + j) * HIDDEN + k];
        #pragma unroll
        for (int j = 0; j < 4; j++) w3r[j] = w3[(4 * g + j) * HIDDEN + k];
        #pragma unroll
        for (int j = 0; j < 4; j++) { va[j] = w1[4 * g + j]; ca[j] = b1[4 * g + j]; }

        float sv = 0.f, sc = 0.f;
        #pragma unroll
        for (int j = 0; j < 4; j++) { sv += va[j] * w2r[j]; sc += ca[j] * w2r[j]; }
        rv[g][k] = sv; rc[g][k] = sc;
        __syncthreads();

        if (g == 0) {
            float v2 = 0.f, c2 = 0.f;
            #pragma unroll
            for (int j = 0; j < 8; j++) { v2 += rv[j][k]; c2 += rc[j][k]; }
            v2s[k] = v2;
            c2s[k] = c2 + b2[k];
        }
        __syncthreads();

        sv = 0.f; sc = 0.f;
        #pragma unroll
        for (int j = 0; j < 4; j++) {
            sv += v2s[4 * g + j] * w3r[j];
            sc += c2s[4 * g + j] * w3r[j];
        }
        rv[g][k] = sv; rc[g][k] = sc;
        __syncthreads();

        if (g == 0) {
            float v3 = 0.f, c3 = 0.f;
            #pragma unroll
            for (int j = 0; j < 8; j++) { v3 += rv[j][k]; c3 += rc[j][k]; }
            c3 += b3[k];
            float a = v3 * w4[k];
            float b = c3 * w4[k];
            #pragma unroll
            for (int off = 16; off > 0; off >>= 1) {
                a += __shfl_xor_sync(0xffffffffu, a, off);
                b += __shfl_xor_sync(0xffffffffu, b, off);
            }
            if (k == 0) {
                g_ab[0] = a;
                g_ab[1] = b + b4[0];
                __threadfence();
                atomicExch(&g_flag, 1);
            }
        }
        return;
    }

    // ================= row blocks: bulk-copy stream ========================
    __shared__ alignas(128) float tile[ROWS_PER_CTA * L];   // 16 KB
    __shared__ alignas(8)  uint64_t mbar;
    __shared__ float sh1[8], sh2[8];

    const int t    = threadIdx.x;
    const int wid  = t >> 5;
    const int lid  = t & 31;
    const int rloc = t >> 7;        // 0 or 1: which of the CTA's two rows
    const int c    = t & 127;       // lane within the row's 128-thread group

    const int row0 = (int)(blockIdx.x - 1) * ROWS_PER_CTA;
    const int row  = row0 + rloc;
    const bool live = (row < rows);

    const uint32_t mbar_a = smem_u32(&mbar);
    const uint32_t tile_a = smem_u32(tile);

    if (t == 0) {
        asm volatile("mbarrier.init.shared.b64 [%0], 1;" :: "r"(mbar_a) : "memory");
    }
    __syncthreads();

    if (t == 0 && row0 < rows) {
        asm volatile("mbarrier.arrive.expect_tx.shared.b64 _, [%0], %1;"
                     :: "r"(mbar_a), "r"(TILE_BYTES) : "memory");
        asm volatile(
            "cp.async.bulk.shared::cluster.global.mbarrier::complete_tx::bytes "
            "[%0], [%1], %2, [%3];"
            :: "r"(tile_a), "l"(x + (size_t)row0 * L), "n"(TILE_BYTES), "r"(mbar_a)
            : "memory");
    }

    // wait (phase 0 — mbarrier freshly initialized every launch)
    if (row0 < rows) {
        uint32_t done;
        asm volatile(
            "{\n\t.reg .pred p;\n\t"
            "mbarrier.try_wait.parity.acquire.cta.shared::cta.b64 p, [%1], 0;\n\t"
            "selp.b32 %0, 1, 0, p;\n\t}"
            : "=r"(done) : "r"(mbar_a) : "memory");
        while (!done) {
            asm volatile(
                "{\n\t.reg .pred p;\n\t"
                "mbarrier.try_wait.parity.acquire.cta.shared::cta.b64 p, [%1], 0, 0x989680;\n\t"
                "selp.b32 %0, 1, 0, p;\n\t}"
                : "=r"(done) : "r"(mbar_a) : "memory");
        }
    }

    // ---- reduce from smem: 4 LDS.128 per thread, conflict-free ----
    float s1 = 0.f, s2 = 0.f;
    if (live) {
        const float4* __restrict__ p = (const float4*)tile + rloc * (L / 4) + c;
        #pragma unroll
        for (int i = 0; i < 4; i++) {
            const float4 v = p[i * 128];
            s1 += (v.x + v.y) + (v.z + v.w);
            s2 += v.x * v.x + v.y * v.y + v.z * v.z + v.w * v.w;
        }
    }

    #pragma unroll
    for (int off = 16; off > 0; off >>= 1) {
        s1 += __shfl_xor_sync(0xffffffffu, s1, off);
        s2 += __shfl_xor_sync(0xffffffffu, s2, off);
    }
    if (lid == 0) { sh1[wid] = s1; sh2[wid] = s2; }

    __syncthreads();

    if (c == 0 && live) {   // t==0 -> row0, t==128 -> row1
        const int base = rloc * 4;
        const float a1 = (sh1[base + 0] + sh1[base + 1]) + (sh1[base + 2] + sh1[base + 3]);
        const float a2 = (sh2[base + 0] + sh2[base + 1]) + (sh2[base + 2] + sh2[base + 3]);

        while (*(volatile int*)&g_flag == 0) { }
        __threadfence();
        const float alpha = *(volatile float*)&g_ab[0];
        const float beta  = *(volatile float*)&g_ab[1];

        out[row] = alpha * a2 / (a1 * a1) + beta;
    }
}

extern "C" void kernel_launch(void* const* d_in, const int* in_sizes, int n_in,
                              void* d_out, int out_size) {
    const float* inc_m = (const float*)d_in[0];
    const float* w1 = (const float*)d_in[1];
    const float* b1 = (const float*)d_in[2];
    const float* w2 = (const float*)d_in[3];
    const float* b2 = (const float*)d_in[4];
    const float* w3 = (const float*)d_in[5];
    const float* b3 = (const float*)d_in[6];
    const float* w4 = (const float*)d_in[7];
    const float* b4 = (const float*)d_in[8];
    float* out = (float*)d_out;

    const int rows = in_sizes[0] / L;                                  // 2048
    const int blocks = 1 + (rows + ROWS_PER_CTA - 1) / ROWS_PER_CTA;   // 1025

    incidence_fused_kernel<<<blocks, THREADS>>>(
        inc_m, w1, b1, w2, b2, w3, b3, w4, b4, out, rows);
}

// round 8
// speedup vs baseline: 1.0332x; 1.0332x over previous
#include <cuda_runtime.h>

// Affine-collapse: weight(x) = alpha*x + beta (4-layer affine MLP, no activations).
// out[row] = alpha * S2/S1^2 + beta, S1 = sum(x), S2 = sum(x^2), row = 2048 floats.
//
// R8 = best measured row structure (R1: one row per 256-thread CTA, 2 front-
// batched float4 loads per thread -> 2.1 TB/s delivery) + fused block-0 weight
// collapse with device flag (R6: no second launch, zero per-CTA weight reads).

#define HIDDEN 32
#define L 2048
#define L_VEC4 (L / 4)   // 512 float4 per row
#define THREADS 256

__device__ float g_ab[2];
__device__ int   g_flag;   // written to the same values every launch -> replays deterministic

__global__ __launch_bounds__(THREADS) void incidence_fused_kernel(
    const float4* __restrict__ x,
    const float* __restrict__ w1, const float* __restrict__ b1,
    const float* __restrict__ w2, const float* __restrict__ b2,
    const float* __restrict__ w3, const float* __restrict__ b3,
    const float* __restrict__ w4, const float* __restrict__ b4,
    float* __restrict__ out)
{
    // ================= block 0: weight collapse, once on the chip ==========
    if (blockIdx.x == 0) {
        __shared__ float rv[8][32], rc[8][32];
        __shared__ float v2s[32], c2s[32];

        const int k = threadIdx.x & 31;   // output unit
        const int g = threadIdx.x >> 5;   // input chunk (4 units each)

        float w2r[4], w3r[4], va[4], ca[4];
        #pragma unroll
        for (int j = 0; j < 4; j++) w2r[j] = w2[(4 * g + j) * HIDDEN + k];
        #pragma unroll
        for (int j = 0; j < 4; j++) w3r[j] = w3[(4 * g + j) * HIDDEN + k];
        #pragma unroll
        for (int j = 0; j < 4; j++) { va[j] = w1[4 * g + j]; ca[j] = b1[4 * g + j]; }

        float sv = 0.f, sc = 0.f;
        #pragma unroll
        for (int j = 0; j < 4; j++) { sv += va[j] * w2r[j]; sc += ca[j] * w2r[j]; }
        rv[g][k] = sv; rc[g][k] = sc;
        __syncthreads();

        if (g == 0) {
            float v2 = 0.f, c2 = 0.f;
            #pragma unroll
            for (int j = 0; j < 8; j++) { v2 += rv[j][k]; c2 += rc[j][k]; }
            v2s[k] = v2;
            c2s[k] = c2 + b2[k];
        }
        __syncthreads();

        sv = 0.f; sc = 0.f;
        #pragma unroll
        for (int j = 0; j < 4; j++) {
            sv += v2s[4 * g + j] * w3r[j];
            sc += c2s[4 * g + j] * w3r[j];
        }
        rv[g][k] = sv; rc[g][k] = sc;
        __syncthreads();

        if (g == 0) {
            float v3 = 0.f, c3 = 0.f;
            #pragma unroll
            for (int j = 0; j < 8; j++) { v3 += rv[j][k]; c3 += rc[j][k]; }
            c3 += b3[k];
            float a = v3 * w4[k];
            float b = c3 * w4[k];
            #pragma unroll
            for (int off = 16; off > 0; off >>= 1) {
                a += __shfl_xor_sync(0xffffffffu, a, off);
                b += __shfl_xor_sync(0xffffffffu, b, off);
            }
            if (k == 0) {
                g_ab[0] = a;
                g_ab[1] = b + b4[0];
                __threadfence();
                atomicExch(&g_flag, 1);
            }
        }
        return;
    }

    // ================= row blocks: one row per CTA (R1 structure) ==========
    const int row = blockIdx.x - 1;
    const float4* __restrict__ p = x + (size_t)row * L_VEC4;
    const int t = threadIdx.x;

    // 2 front-batched float4 loads per thread
    const float4 v0 = p[t];
    const float4 v1 = p[t + 256];

    float s1, s2;
    s1  = (v0.x + v0.y) + (v0.z + v0.w);
    s2  = v0.x * v0.x + v0.y * v0.y + v0.z * v0.z + v0.w * v0.w;
    s1 += (v1.x + v1.y) + (v1.z + v1.w);
    s2 += v1.x * v1.x + v1.y * v1.y + v1.z * v1.z + v1.w * v1.w;

    // warp reduce
    #pragma unroll
    for (int off = 16; off > 0; off >>= 1) {
        s1 += __shfl_xor_sync(0xffffffffu, s1, off);
        s2 += __shfl_xor_sync(0xffffffffu, s2, off);
    }

    __shared__ float sh1[8], sh2[8];
    const int w = t >> 5, l = t & 31;
    if (l == 0) { sh1[w] = s1; sh2[w] = s2; }
    __syncthreads();

    if (t < 8) {
        float a = sh1[t], b = sh2[t];
        #pragma unroll
        for (int off = 4; off > 0; off >>= 1) {
            a += __shfl_xor_sync(0xffu, a, off);
            b += __shfl_xor_sync(0xffu, b, off);
        }
        if (t == 0) {
            while (*(volatile int*)&g_flag == 0) { }
            __threadfence();
            const float alpha = *(volatile float*)&g_ab[0];
            const float beta  = *(volatile float*)&g_ab[1];
            out[row] = alpha * b / (a * a) + beta;
        }
    }
}

extern "C" void kernel_launch(void* const* d_in, const int* in_sizes, int n_in,
                              void* d_out, int out_size) {
    const float* inc_m = (const float*)d_in[0];
    const float* w1 = (const float*)d_in[1];
    const float* b1 = (const float*)d_in[2];
    const float* w2 = (const float*)d_in[3];
    const float* b2 = (const float*)d_in[4];
    const float* w3 = (const float*)d_in[5];
    const float* b3 = (const float*)d_in[6];
    const float* w4 = (const float*)d_in[7];
    const float* b4 = (const float*)d_in[8];
    float* out = (float*)d_out;

    const int rows = in_sizes[0] / L;   // B*F = 2048

    incidence_fused_kernel<<<rows + 1, THREADS>>>(
        (const float4*)inc_m, w1, b1, w2, b2, w3, b3, w4, b4, out);
}